// round 16
// baseline (speedup 1.0000x reference)
#include <cuda_runtime.h>
#include <cuda_bf16.h>
#include <cstdint>

#define MAX_NODES 100000
#define MAX_EDGES 1600000
#define D 64
#define D2 (D / 2)

// ---------------------------------------------------------------------------
// Scratch (allocation-free rule -> device globals). All zero-init at load;
// every launch restores the zero-invariants it consumes (see gather_h /
// fill_elist), so graph replays are deterministic.
// ---------------------------------------------------------------------------
__device__ int g_deg[MAX_NODES];      // zeroed by gather_h after last use
__device__ int g_off[MAX_NODES];
__device__ int g_cursor[MAX_NODES];
__device__ int g_aggr[128];           // scan block aggregates
__device__ int g_flagv[128];          // publish flags; reset by fill_elist
__device__ int g_elist[MAX_EDGES];
__device__ float2 g_h2[(size_t)MAX_NODES * D2];   // normalized neighbor means

// ---------------------------------------------------------------------------
// K1: count in-degree per dst (int32 indices). g_deg starts all-zero.
// ---------------------------------------------------------------------------
__global__ void count_deg(const int* __restrict__ dst, int e) {
    int i = blockIdx.x * blockDim.x + threadIdx.x;
    if (i < e) atomicAdd(&g_deg[dst[i]], 1);
}

// ---------------------------------------------------------------------------
// K2: single-kernel exclusive scan of g_deg -> g_off, g_cursor.
// grid = ceil(n/1024) <= 98 blocks -> ALL co-resident on 148 SMs, so the
// publish-then-poll cross-block prefix cannot deadlock: every block first
// publishes its own aggregate, then waits only on earlier blocks.
// ---------------------------------------------------------------------------
__global__ __launch_bounds__(1024) void scan_fused(int n) {
    __shared__ int s[1024];
    __shared__ int pre[128];
    int tid = threadIdx.x;
    int bid = blockIdx.x;
    int i = bid * 1024 + tid;
    int v = (i < n) ? g_deg[i] : 0;
    s[tid] = v;
    __syncthreads();
#pragma unroll
    for (int ofs = 1; ofs < 1024; ofs <<= 1) {
        int t = (tid >= ofs) ? s[tid - ofs] : 0;
        __syncthreads();
        s[tid] += t;
        __syncthreads();
    }
    int local_excl = s[tid] - v;
    // publish this block's total BEFORE polling others
    if (tid == 1023) {
        g_aggr[bid] = s[1023];
        __threadfence();
        atomicExch(&g_flagv[bid], 1);
    }
    // poll earlier blocks' aggregates (one flag per thread)
    if (tid < 128) {
        int p = 0;
        if (tid < bid) {
            while (atomicAdd(&g_flagv[tid], 0) == 0) { }
            p = atomicAdd(&g_aggr[tid], 0);
        }
        pre[tid] = p;
    }
    __syncthreads();
#pragma unroll
    for (int ofs = 64; ofs > 0; ofs >>= 1) {
        if (tid < ofs) pre[tid] += pre[tid + ofs];
        __syncthreads();
    }
    int prefix = pre[0];
    if (i < n) {
        int o = local_excl + prefix;
        g_off[i] = o;
        g_cursor[i] = o;
    }
}

// ---------------------------------------------------------------------------
// K3: fill per-dst edge lists; also resets the scan flags (safe: stream order
// guarantees scan_fused fully completed before this kernel starts).
// ---------------------------------------------------------------------------
__global__ void fill_elist(const int* __restrict__ src,
                           const int* __restrict__ dst, int e) {
    int i = blockIdx.x * blockDim.x + threadIdx.x;
    if (i < 128) { g_flagv[i] = 0; g_aggr[i] = 0; }
    if (i < e) {
        int d = dst[i];
        int pos = atomicAdd(&g_cursor[d], 1);
        g_elist[pos] = src[i];
    }
}

// ---------------------------------------------------------------------------
// K4: gather (fp32). One warp per node; lane = float2 chunk.
// Last reader of g_deg -> re-zeroes it for the next launch (restores the
// module-load zero invariant; identical work every launch).
// ---------------------------------------------------------------------------
__global__ __launch_bounds__(256)
void gather_h(const float2* __restrict__ feat2, int n) {
    int warp = (blockIdx.x * 256 + threadIdx.x) >> 5;
    int lane = threadIdx.x & 31;
    if (warp >= n) return;
    int node  = warp;
    int start = g_off[node];
    int g     = g_deg[node];
    if (lane == 0) g_deg[node] = 0;              // self-clean for next launch

    float2 acc = make_float2(0.f, 0.f);
    int k = 0;
    for (; k + 4 <= g; k += 4) {
        int s0 = g_elist[start + k + 0];
        int s1 = g_elist[start + k + 1];
        int s2 = g_elist[start + k + 2];
        int s3 = g_elist[start + k + 3];
        float2 v0 = feat2[(size_t)s0 * D2 + lane];
        float2 v1 = feat2[(size_t)s1 * D2 + lane];
        float2 v2 = feat2[(size_t)s2 * D2 + lane];
        float2 v3 = feat2[(size_t)s3 * D2 + lane];
        acc.x += v0.x + v1.x + v2.x + v3.x;
        acc.y += v0.y + v1.y + v2.y + v3.y;
    }
    for (; k < g; k++) {
        int s0 = g_elist[start + k];
        float2 v0 = feat2[(size_t)s0 * D2 + lane];
        acc.x += v0.x; acc.y += v0.y;
    }
    float inv = 1.0f / (float)max(g, 1);
    acc.x *= inv; acc.y *= inv;
    g_h2[(size_t)node * D2 + lane] = acc;
}

// ---------------------------------------------------------------------------
// K5: tf32 mma.sync dual GEMM + bias + ReLU (unchanged from R14 WIN).
// ---------------------------------------------------------------------------
#define SROWF 68                        // smem row stride in floats

#define OFF_WS   0                              // Wt_self [64][68] f32
#define OFF_WN   (OFF_WS + 64 * SROWF * 4)      // Wt_neigh
#define OFF_AF   (OFF_WN + 64 * SROWF * 4)      // feat tile [128][68]
#define OFF_AH   (OFF_AF + 128 * SROWF * 4)     // h tile
#define OFF_BIAS (OFF_AH + 128 * SROWF * 4)     // bias [64]
#define SMEM_GEMM_BYTES (OFF_BIAS + 256)

__device__ __forceinline__ uint32_t tf32r(float x) {
    uint32_t r;
    asm("cvt.rna.tf32.f32 %0, %1;" : "=r"(r) : "f"(x));
    return r;
}

__device__ __forceinline__ void mma_tf32(float c[4], const uint32_t a[4],
                                         const uint32_t b[2]) {
    asm volatile(
        "mma.sync.aligned.m16n8k8.row.col.f32.tf32.tf32.f32 "
        "{%0,%1,%2,%3}, {%4,%5,%6,%7}, {%8,%9}, {%0,%1,%2,%3};"
        : "+f"(c[0]), "+f"(c[1]), "+f"(c[2]), "+f"(c[3])
        : "r"(a[0]), "r"(a[1]), "r"(a[2]), "r"(a[3]), "r"(b[0]), "r"(b[1]));
}

__global__ __launch_bounds__(128)
void sage_gemm(const float4* __restrict__ feat4,
               const float* __restrict__ W_self,
               const float* __restrict__ W_neigh,
               const float* __restrict__ bias,
               float* __restrict__ out,
               int n) {
    extern __shared__ __align__(16) char smem[];
    float* sWS = reinterpret_cast<float*>(smem + OFF_WS);   // [j][k], stride 68
    float* sWN = reinterpret_cast<float*>(smem + OFF_WN);
    float* sAF = reinterpret_cast<float*>(smem + OFF_AF);   // [row][k], stride 68
    float* sAH = reinterpret_cast<float*>(smem + OFF_AH);
    float* sB  = reinterpret_cast<float*>(smem + OFF_BIAS);

    int tid  = threadIdx.x;
    int base = blockIdx.x * 128;

    // ---- stage weights transposed (Wt[j][k] = W[k][j]), tf32-rounded ----
#pragma unroll
    for (int q = 0; q < 32; q++) {
        int i = tid + 128 * q;          // 4096 = 64k x 64j
        int k = i >> 6, j = i & 63;
        sWS[j * SROWF + k] = __uint_as_float(tf32r(W_self[i]));
        sWN[j * SROWF + k] = __uint_as_float(tf32r(W_neigh[i]));
    }

    // ---- stage feat / h tiles (128 rows), tf32-rounded ----
    {
        const float4* h4 = reinterpret_cast<const float4*>(g_h2);
        float4 fz = make_float4(0.f, 0.f, 0.f, 0.f);
#pragma unroll
        for (int q = 0; q < 16; q++) {
            int idx = tid + 128 * q;    // 2048 = 128 rows x 16 float4
            int row = idx >> 4, c4 = idx & 15;
            int gn  = base + row;
            float4 fv = fz, hv = fz;
            if (gn < n) {
                fv = feat4[(size_t)gn * 16 + c4];
                hv = h4[(size_t)gn * 16 + c4];
            }
            float4 ft, ht;
            ft.x = __uint_as_float(tf32r(fv.x)); ft.y = __uint_as_float(tf32r(fv.y));
            ft.z = __uint_as_float(tf32r(fv.z)); ft.w = __uint_as_float(tf32r(fv.w));
            ht.x = __uint_as_float(tf32r(hv.x)); ht.y = __uint_as_float(tf32r(hv.y));
            ht.z = __uint_as_float(tf32r(hv.z)); ht.w = __uint_as_float(tf32r(hv.w));
            *reinterpret_cast<float4*>(&sAF[row * SROWF + c4 * 4]) = ft;
            *reinterpret_cast<float4*>(&sAH[row * SROWF + c4 * 4]) = ht;
        }
    }
    if (tid < 64) sB[tid] = bias[tid];
    __syncthreads();

    // ---- per-warp MMA: rows m0..m0+31, cols 0..63 ----
    int wid = tid >> 5;
    int lane = tid & 31;
    int qr = lane >> 2;                 // group id 0..7
    int qc = lane & 3;                  // thread-in-group 0..3
    int m0 = wid * 32;

    float c[2][8][4];
#pragma unroll
    for (int mt = 0; mt < 2; mt++)
#pragma unroll
        for (int nb = 0; nb < 8; nb++)
#pragma unroll
            for (int x = 0; x < 4; x++) c[mt][nb][x] = 0.f;

#pragma unroll
    for (int k8 = 0; k8 < 8; k8++) {
        int kb = k8 * 8;

        uint32_t bs[8][2], bn[8][2];
#pragma unroll
        for (int nb = 0; nb < 8; nb++) {
            int nrow = nb * 8 + qr;
            bs[nb][0] = __float_as_uint(sWS[nrow * SROWF + kb + qc]);
            bs[nb][1] = __float_as_uint(sWS[nrow * SROWF + kb + qc + 4]);
            bn[nb][0] = __float_as_uint(sWN[nrow * SROWF + kb + qc]);
            bn[nb][1] = __float_as_uint(sWN[nrow * SROWF + kb + qc + 4]);
        }

#pragma unroll
        for (int mt = 0; mt < 2; mt++) {
            int mr = m0 + mt * 16 + qr;
            uint32_t af[4], ah[4];
            af[0] = __float_as_uint(sAF[mr * SROWF + kb + qc]);
            af[1] = __float_as_uint(sAF[(mr + 8) * SROWF + kb + qc]);
            af[2] = __float_as_uint(sAF[mr * SROWF + kb + qc + 4]);
            af[3] = __float_as_uint(sAF[(mr + 8) * SROWF + kb + qc + 4]);
            ah[0] = __float_as_uint(sAH[mr * SROWF + kb + qc]);
            ah[1] = __float_as_uint(sAH[(mr + 8) * SROWF + kb + qc]);
            ah[2] = __float_as_uint(sAH[mr * SROWF + kb + qc + 4]);
            ah[3] = __float_as_uint(sAH[(mr + 8) * SROWF + kb + qc + 4]);
#pragma unroll
            for (int nb = 0; nb < 8; nb++) {
                mma_tf32(c[mt][nb], af, bs[nb]);
                mma_tf32(c[mt][nb], ah, bn[nb]);
            }
        }
    }

    // ---- epilogue: bias + ReLU + store ----
#pragma unroll
    for (int mt = 0; mt < 2; mt++) {
#pragma unroll
        for (int nb = 0; nb < 8; nb++) {
            int col = nb * 8 + 2 * qc;
            float b0 = sB[col], b1 = sB[col + 1];
            int r0 = base + m0 + mt * 16 + qr;
            int r1 = r0 + 8;
            if (r0 < n) {
                float2 v;
                v.x = fmaxf(c[mt][nb][0] + b0, 0.f);
                v.y = fmaxf(c[mt][nb][1] + b1, 0.f);
                *reinterpret_cast<float2*>(out + (size_t)r0 * D + col) = v;
            }
            if (r1 < n) {
                float2 v;
                v.x = fmaxf(c[mt][nb][2] + b0, 0.f);
                v.y = fmaxf(c[mt][nb][3] + b1, 0.f);
                *reinterpret_cast<float2*>(out + (size_t)r1 * D + col) = v;
            }
        }
    }
}

// ---------------------------------------------------------------------------
// Launch.  Inputs: feat[N*64] f32, src[E] i32, dst[E] i32,
//                  W_self[64*64] f32, W_neigh[64*64] f32, bias[64] f32
// ---------------------------------------------------------------------------
extern "C" void kernel_launch(void* const* d_in, const int* in_sizes, int n_in,
                              void* d_out, int out_size) {
    const float* feat    = (const float*)d_in[0];
    const int*   src     = (const int*)d_in[1];
    const int*   dst     = (const int*)d_in[2];
    const float* W_self  = (const float*)d_in[3];
    const float* W_neigh = (const float*)d_in[4];
    const float* bias    = (const float*)d_in[5];
    float*       out     = (float*)d_out;

    int n = in_sizes[0] / D;
    int e = in_sizes[1];

    int eb256  = (e + 255) / 256;
    int nScanB = (n + 1023) / 1024;

    count_deg<<<eb256, 256>>>(dst, e);
    scan_fused<<<nScanB, 1024>>>(n);
    fill_elist<<<eb256, 256>>>(src, dst, e);

    int gblocks = (n + 7) / 8;                    // one warp per node
    gather_h<<<gblocks, 256>>>(reinterpret_cast<const float2*>(feat), n);

    static int smem_set = 0;
    if (!smem_set) {
        cudaFuncSetAttribute(sage_gemm, cudaFuncAttributeMaxDynamicSharedMemorySize,
                             SMEM_GEMM_BYTES);
        smem_set = 1;
    }
    int gemmBlocks = (n + 127) / 128;
    sage_gemm<<<gemmBlocks, 128, SMEM_GEMM_BYTES>>>(
        reinterpret_cast<const float4*>(feat), W_self, W_neigh, bias, out, n);
}

// round 17
// speedup vs baseline: 1.0116x; 1.0116x over previous
#include <cuda_runtime.h>
#include <cuda_bf16.h>
#include <cstdint>

#define MAX_NODES 100000
#define MAX_EDGES 1600000
#define D 64
#define D2 (D / 2)

// ---------------------------------------------------------------------------
// Scratch (allocation-free rule -> device globals). g_deg is zero at module
// load and re-zeroed by gather_h (its last reader) every launch, so each
// launch sees the same initial state (graph-replay deterministic).
// ---------------------------------------------------------------------------
__device__ int g_deg[MAX_NODES];
__device__ int g_off[MAX_NODES];
__device__ int g_cursor[MAX_NODES];
__device__ int g_bsum[1024];
__device__ int g_elist[MAX_EDGES];
__device__ float2 g_h2[(size_t)MAX_NODES * D2];   // normalized neighbor means

// ---------------------------------------------------------------------------
// K1: count in-degree per dst (int32 indices). g_deg is all-zero on entry.
// ---------------------------------------------------------------------------
__global__ void count_deg(const int* __restrict__ dst, int e) {
    int i = blockIdx.x * blockDim.x + threadIdx.x;
    if (i < e) atomicAdd(&g_deg[dst[i]], 1);
}

// ---------------------------------------------------------------------------
// K2a: per-1024-block exclusive scan; block totals -> g_bsum
// ---------------------------------------------------------------------------
__global__ __launch_bounds__(1024) void scan_blocks(int n) {
    __shared__ int s[1024];
    int tid = threadIdx.x;
    int i = blockIdx.x * 1024 + tid;
    int v = (i < n) ? g_deg[i] : 0;
    s[tid] = v;
    __syncthreads();
#pragma unroll
    for (int ofs = 1; ofs < 1024; ofs <<= 1) {
        int t = (tid >= ofs) ? s[tid - ofs] : 0;
        __syncthreads();
        s[tid] += t;
        __syncthreads();
    }
    if (i < n) g_off[i] = s[tid] - v;            // exclusive within block
    if (tid == 1023) g_bsum[blockIdx.x] = s[1023];
}

// ---------------------------------------------------------------------------
// K2b: add block-prefix (inline reduction of <=98 block sums)
// ---------------------------------------------------------------------------
__global__ __launch_bounds__(256) void scan_add(int n) {
    __shared__ int red[256];
    int t = threadIdx.x;
    int group = blockIdx.x >> 2;                  // # of bsums before us (<= 98)
    red[t] = (t < group) ? g_bsum[t] : 0;
    __syncthreads();
#pragma unroll
    for (int ofs = 128; ofs > 0; ofs >>= 1) {
        if (t < ofs) red[t] += red[t + ofs];
        __syncthreads();
    }
    int prefix = red[0];
    int i = blockIdx.x * 256 + t;
    if (i < n) {
        int o = g_off[i] + prefix;
        g_off[i] = o;
        g_cursor[i] = o;
    }
}

// ---------------------------------------------------------------------------
// K3: fill per-dst edge lists (src ids, grouped by dst)
// ---------------------------------------------------------------------------
__global__ void fill_elist(const int* __restrict__ src,
                           const int* __restrict__ dst, int e) {
    int i = blockIdx.x * blockDim.x + threadIdx.x;
    if (i < e) {
        int d = dst[i];
        int pos = atomicAdd(&g_cursor[d], 1);
        g_elist[pos] = src[i];
    }
}

// ---------------------------------------------------------------------------
// K4: gather (fp32). One warp per node; lane = float2 chunk.
// Last reader of g_deg -> re-zeroes it (replaces the zero_deg kernel).
// ---------------------------------------------------------------------------
__global__ __launch_bounds__(256)
void gather_h(const float2* __restrict__ feat2, int n) {
    int warp = (blockIdx.x * 256 + threadIdx.x) >> 5;
    int lane = threadIdx.x & 31;
    if (warp >= n) return;
    int node  = warp;
    int start = g_off[node];
    int g     = g_deg[node];
    if (lane == 0) g_deg[node] = 0;              // restore zero-invariant

    float2 acc = make_float2(0.f, 0.f);
    int k = 0;
    for (; k + 4 <= g; k += 4) {
        int s0 = g_elist[start + k + 0];
        int s1 = g_elist[start + k + 1];
        int s2 = g_elist[start + k + 2];
        int s3 = g_elist[start + k + 3];
        float2 v0 = feat2[(size_t)s0 * D2 + lane];
        float2 v1 = feat2[(size_t)s1 * D2 + lane];
        float2 v2 = feat2[(size_t)s2 * D2 + lane];
        float2 v3 = feat2[(size_t)s3 * D2 + lane];
        acc.x += v0.x + v1.x + v2.x + v3.x;
        acc.y += v0.y + v1.y + v2.y + v3.y;
    }
    for (; k < g; k++) {
        int s0 = g_elist[start + k];
        float2 v0 = feat2[(size_t)s0 * D2 + lane];
        acc.x += v0.x; acc.y += v0.y;
    }
    float inv = 1.0f / (float)max(g, 1);
    acc.x *= inv; acc.y *= inv;
    g_h2[(size_t)node * D2 + lane] = acc;
}

// ---------------------------------------------------------------------------
// K5: tf32 mma.sync dual GEMM + bias + ReLU (unchanged from R14 WIN).
// ---------------------------------------------------------------------------
#define SROWF 68                        // smem row stride in floats

#define OFF_WS   0                              // Wt_self [64][68] f32
#define OFF_WN   (OFF_WS + 64 * SROWF * 4)      // Wt_neigh
#define OFF_AF   (OFF_WN + 64 * SROWF * 4)      // feat tile [128][68]
#define OFF_AH   (OFF_AF + 128 * SROWF * 4)     // h tile
#define OFF_BIAS (OFF_AH + 128 * SROWF * 4)     // bias [64]
#define SMEM_GEMM_BYTES (OFF_BIAS + 256)

__device__ __forceinline__ uint32_t tf32r(float x) {
    uint32_t r;
    asm("cvt.rna.tf32.f32 %0, %1;" : "=r"(r) : "f"(x));
    return r;
}

__device__ __forceinline__ void mma_tf32(float c[4], const uint32_t a[4],
                                         const uint32_t b[2]) {
    asm volatile(
        "mma.sync.aligned.m16n8k8.row.col.f32.tf32.tf32.f32 "
        "{%0,%1,%2,%3}, {%4,%5,%6,%7}, {%8,%9}, {%0,%1,%2,%3};"
        : "+f"(c[0]), "+f"(c[1]), "+f"(c[2]), "+f"(c[3])
        : "r"(a[0]), "r"(a[1]), "r"(a[2]), "r"(a[3]), "r"(b[0]), "r"(b[1]));
}

__global__ __launch_bounds__(128)
void sage_gemm(const float4* __restrict__ feat4,
               const float* __restrict__ W_self,
               const float* __restrict__ W_neigh,
               const float* __restrict__ bias,
               float* __restrict__ out,
               int n) {
    extern __shared__ __align__(16) char smem[];
    float* sWS = reinterpret_cast<float*>(smem + OFF_WS);   // [j][k], stride 68
    float* sWN = reinterpret_cast<float*>(smem + OFF_WN);
    float* sAF = reinterpret_cast<float*>(smem + OFF_AF);   // [row][k], stride 68
    float* sAH = reinterpret_cast<float*>(smem + OFF_AH);
    float* sB  = reinterpret_cast<float*>(smem + OFF_BIAS);

    int tid  = threadIdx.x;
    int base = blockIdx.x * 128;

    // ---- stage weights transposed (Wt[j][k] = W[k][j]), tf32-rounded ----
#pragma unroll
    for (int q = 0; q < 32; q++) {
        int i = tid + 128 * q;          // 4096 = 64k x 64j
        int k = i >> 6, j = i & 63;
        sWS[j * SROWF + k] = __uint_as_float(tf32r(W_self[i]));
        sWN[j * SROWF + k] = __uint_as_float(tf32r(W_neigh[i]));
    }

    // ---- stage feat / h tiles (128 rows), tf32-rounded ----
    {
        const float4* h4 = reinterpret_cast<const float4*>(g_h2);
        float4 fz = make_float4(0.f, 0.f, 0.f, 0.f);
#pragma unroll
        for (int q = 0; q < 16; q++) {
            int idx = tid + 128 * q;    // 2048 = 128 rows x 16 float4
            int row = idx >> 4, c4 = idx & 15;
            int gn  = base + row;
            float4 fv = fz, hv = fz;
            if (gn < n) {
                fv = feat4[(size_t)gn * 16 + c4];
                hv = h4[(size_t)gn * 16 + c4];
            }
            float4 ft, ht;
            ft.x = __uint_as_float(tf32r(fv.x)); ft.y = __uint_as_float(tf32r(fv.y));
            ft.z = __uint_as_float(tf32r(fv.z)); ft.w = __uint_as_float(tf32r(fv.w));
            ht.x = __uint_as_float(tf32r(hv.x)); ht.y = __uint_as_float(tf32r(hv.y));
            ht.z = __uint_as_float(tf32r(hv.z)); ht.w = __uint_as_float(tf32r(hv.w));
            *reinterpret_cast<float4*>(&sAF[row * SROWF + c4 * 4]) = ft;
            *reinterpret_cast<float4*>(&sAH[row * SROWF + c4 * 4]) = ht;
        }
    }
    if (tid < 64) sB[tid] = bias[tid];
    __syncthreads();

    // ---- per-warp MMA: rows m0..m0+31, cols 0..63 ----
    int wid = tid >> 5;
    int lane = tid & 31;
    int qr = lane >> 2;                 // group id 0..7
    int qc = lane & 3;                  // thread-in-group 0..3
    int m0 = wid * 32;

    float c[2][8][4];
#pragma unroll
    for (int mt = 0; mt < 2; mt++)
#pragma unroll
        for (int nb = 0; nb < 8; nb++)
#pragma unroll
            for (int x = 0; x < 4; x++) c[mt][nb][x] = 0.f;

#pragma unroll
    for (int k8 = 0; k8 < 8; k8++) {
        int kb = k8 * 8;

        uint32_t bs[8][2], bn[8][2];
#pragma unroll
        for (int nb = 0; nb < 8; nb++) {
            int nrow = nb * 8 + qr;
            bs[nb][0] = __float_as_uint(sWS[nrow * SROWF + kb + qc]);
            bs[nb][1] = __float_as_uint(sWS[nrow * SROWF + kb + qc + 4]);
            bn[nb][0] = __float_as_uint(sWN[nrow * SROWF + kb + qc]);
            bn[nb][1] = __float_as_uint(sWN[nrow * SROWF + kb + qc + 4]);
        }

#pragma unroll
        for (int mt = 0; mt < 2; mt++) {
            int mr = m0 + mt * 16 + qr;
            uint32_t af[4], ah[4];
            af[0] = __float_as_uint(sAF[mr * SROWF + kb + qc]);
            af[1] = __float_as_uint(sAF[(mr + 8) * SROWF + kb + qc]);
            af[2] = __float_as_uint(sAF[mr * SROWF + kb + qc + 4]);
            af[3] = __float_as_uint(sAF[(mr + 8) * SROWF + kb + qc + 4]);
            ah[0] = __float_as_uint(sAH[mr * SROWF + kb + qc]);
            ah[1] = __float_as_uint(sAH[(mr + 8) * SROWF + kb + qc]);
            ah[2] = __float_as_uint(sAH[mr * SROWF + kb + qc + 4]);
            ah[3] = __float_as_uint(sAH[(mr + 8) * SROWF + kb + qc + 4]);
#pragma unroll
            for (int nb = 0; nb < 8; nb++) {
                mma_tf32(c[mt][nb], af, bs[nb]);
                mma_tf32(c[mt][nb], ah, bn[nb]);
            }
        }
    }

    // ---- epilogue: bias + ReLU + store ----
#pragma unroll
    for (int mt = 0; mt < 2; mt++) {
#pragma unroll
        for (int nb = 0; nb < 8; nb++) {
            int col = nb * 8 + 2 * qc;
            float b0 = sB[col], b1 = sB[col + 1];
            int r0 = base + m0 + mt * 16 + qr;
            int r1 = r0 + 8;
            if (r0 < n) {
                float2 v;
                v.x = fmaxf(c[mt][nb][0] + b0, 0.f);
                v.y = fmaxf(c[mt][nb][1] + b1, 0.f);
                *reinterpret_cast<float2*>(out + (size_t)r0 * D + col) = v;
            }
            if (r1 < n) {
                float2 v;
                v.x = fmaxf(c[mt][nb][2] + b0, 0.f);
                v.y = fmaxf(c[mt][nb][3] + b1, 0.f);
                *reinterpret_cast<float2*>(out + (size_t)r1 * D + col) = v;
            }
        }
    }
}

// ---------------------------------------------------------------------------
// Launch.  Inputs: feat[N*64] f32, src[E] i32, dst[E] i32,
//                  W_self[64*64] f32, W_neigh[64*64] f32, bias[64] f32
// ---------------------------------------------------------------------------
extern "C" void kernel_launch(void* const* d_in, const int* in_sizes, int n_in,
                              void* d_out, int out_size) {
    const float* feat    = (const float*)d_in[0];
    const int*   src     = (const int*)d_in[1];
    const int*   dst     = (const int*)d_in[2];
    const float* W_self  = (const float*)d_in[3];
    const float* W_neigh = (const float*)d_in[4];
    const float* bias    = (const float*)d_in[5];
    float*       out     = (float*)d_out;

    int n = in_sizes[0] / D;
    int e = in_sizes[1];

    int eb256  = (e + 255) / 256;
    int nScanB = (n + 1023) / 1024;

    count_deg<<<eb256, 256>>>(dst, e);
    scan_blocks<<<nScanB, 1024>>>(n);
    scan_add<<<(n + 255) / 256, 256>>>(n);
    fill_elist<<<eb256, 256>>>(src, dst, e);

    int gblocks = (n + 7) / 8;                    // one warp per node
    gather_h<<<gblocks, 256>>>(reinterpret_cast<const float2*>(feat), n);

    static int smem_set = 0;
    if (!smem_set) {
        cudaFuncSetAttribute(sage_gemm, cudaFuncAttributeMaxDynamicSharedMemorySize,
                             SMEM_GEMM_BYTES);
        smem_set = 1;
    }
    int gemmBlocks = (n + 127) / 128;
    sage_gemm<<<gemmBlocks, 128, SMEM_GEMM_BYTES>>>(
        reinterpret_cast<const float4*>(feat), W_self, W_neigh, bias, out, n);
}